// round 11
// baseline (speedup 1.0000x reference)
#include <cuda_runtime.h>
#include <math.h>

#define MAXN 100000
#define MAXE 1600000

// ---------------- static device scratch (device-code use ONLY) -----------------
__device__ int   g_deg[MAXN];
__device__ int   g_off[MAXN + 1];
__device__ int   g_cur[MAXN];
__device__ int   g_srcA[MAXE];       // CSR: incoming-edge sources per dst node
__device__ float g_norm[MAXN];
__device__ float g_t0[MAXN * 64];    // message ping buffer
__device__ float g_t1[MAXN * 64];    // message pong buffer

// ---------------- graph preprocessing ------------------------------------------
__global__ void kz_deg(int n) {
    int i = blockIdx.x * blockDim.x + threadIdx.x;
    if (i < n) g_deg[i] = 0;
}
__global__ void kfill_out(float* __restrict__ p, int c) {
    int i = blockIdx.x * blockDim.x + threadIdx.x;
    if (i < c) p[i] = 0.0f;
}
__global__ void kdeg(const int* __restrict__ dst, int E) {
    int e = blockIdx.x * blockDim.x + threadIdx.x;
    if (e < E) atomicAdd(&g_deg[dst[e]], 1);
}
__global__ void knorm(int n) {
    int i = blockIdx.x * blockDim.x + threadIdx.x;
    if (i < n) g_norm[i] = rsqrtf(fmaxf((float)g_deg[i], 1.0f));
}

// single-block exclusive scan of g_deg[0..N) -> g_off, g_cur
__global__ void kscan(int N) {
    const int T = 1024;
    int tid = threadIdx.x;
    int per = (N + T - 1) / T;
    int s = tid * per; if (s > N) s = N;
    int e = s + per;   if (e > N) e = N;
    int sum = 0;
    for (int i = s; i < e; i++) sum += g_deg[i];
    __shared__ int sh[T];
    sh[tid] = sum;
    __syncthreads();
    for (int off = 1; off < T; off <<= 1) {
        int v = (tid >= off) ? sh[tid - off] : 0;
        __syncthreads();
        sh[tid] += v;
        __syncthreads();
    }
    int run = (tid == 0) ? 0 : sh[tid - 1];
    for (int i = s; i < e; i++) {
        g_off[i] = run;
        g_cur[i] = run;
        run += g_deg[i];
    }
    if (tid == T - 1) g_off[N] = run;
}

__global__ void kcsr(const int* __restrict__ src, const int* __restrict__ dst, int E) {
    int e = blockIdx.x * blockDim.x + threadIdx.x;
    if (e < E) {
        int p = atomicAdd(&g_cur[dst[e]], 1);
        g_srcA[p] = src[e];
    }
}

__global__ void kt0(const float* __restrict__ x, int c) {
    int i = blockIdx.x * blockDim.x + threadIdx.x;
    if (i < c) g_t0[i] = x[i] * g_norm[i >> 6];
}

// ---------------- fused layer: aggregate(CSR pull) + GEMM + epilogue ------------
// 256 threads; tile 128 dst nodes x 64 outs.
// pp selects message buffers IN DEVICE CODE: read g_t[pp], write g_t[pp^1].
// Phase 1: 8 warps, warp w aggregates nodes [w*16, w*16+16) into Asm (agg*norm).
// Phase 2: GEMM: thread = 4 nodes x 8 outs.
// EPI 0: relu * norm -> tout (stride 64)
// EPI 1: Wa=W31, Wb=W32: mu -> o0, lv -> o1 (if have), z*norm -> tout (stride 32)
// EPI 2: sigmoid -> o0 (recon)
template <int K, int EPI>
__global__ __launch_bounds__(256) void kfused(
    const float* __restrict__ Wa, const float* __restrict__ Wb,
    const float* __restrict__ bias0, const float* __restrict__ bias1,
    float* __restrict__ o0, float* __restrict__ o1, const float* __restrict__ eps,
    int N, int have, int pp)
{
    extern __shared__ float sm[];
    float* Asm = sm;                  // 128 * 65  (agg tile, stride-65 pad)
    float* Wsm = sm + 128 * 65;       // K * 64    (Wsm[k*64+o] = W[o][k])
    float* Bsm = Wsm + K * 64;        // 64
    const int tid = threadIdx.x;
    const int base = blockIdx.x * 128;

    const float* __restrict__ tin = pp ? g_t1 : g_t0;
    float* __restrict__ tout      = pp ? g_t0 : g_t1;

    // stage W transposed + bias
    for (int q = tid; q < K * 64; q += 256) {
        int k = q >> 6, o = q & 63;
        float w;
        if (EPI == 1) w = (o < 32) ? Wa[o * 64 + k] : Wb[(o - 32) * 64 + k];
        else          w = Wa[o * K + k];
        Wsm[q] = w;
    }
    if (tid < 64) {
        if (EPI == 1) Bsm[tid] = (tid < 32) ? bias0[tid] : bias1[tid - 32];
        else          Bsm[tid] = bias0[tid];
    }

    // ---- Phase 1: aggregation into Asm ----
    const int wd = tid >> 5, lane = tid & 31;
#pragma unroll 1
    for (int t = 0; t < 16; t++) {
        int nl = wd * 16 + t;          // local node 0..127
        int n = base + nl;
        if (n < N) {
            int bo = g_off[n], eo = g_off[n + 1];
            float nm = g_norm[n];
            if (K == 64) {
                const float2* tp = (const float2*)tin;
                float ax = 0.f, ay = 0.f;
                int i = bo;
                for (; i + 4 <= eo; i += 4) {
                    int s0 = g_srcA[i], s1 = g_srcA[i + 1], s2 = g_srcA[i + 2], s3 = g_srcA[i + 3];
                    float2 v0 = tp[s0 * 32 + lane];
                    float2 v1 = tp[s1 * 32 + lane];
                    float2 v2 = tp[s2 * 32 + lane];
                    float2 v3 = tp[s3 * 32 + lane];
                    ax += (v0.x + v1.x) + (v2.x + v3.x);
                    ay += (v0.y + v1.y) + (v2.y + v3.y);
                }
                for (; i < eo; i++) {
                    float2 v = tp[g_srcA[i] * 32 + lane];
                    ax += v.x; ay += v.y;
                }
                Asm[nl * 65 + 2 * lane]     = ax * nm;
                Asm[nl * 65 + 2 * lane + 1] = ay * nm;
            } else {
                float a = 0.f;
                int i = bo;
                for (; i + 4 <= eo; i += 4) {
                    int s0 = g_srcA[i], s1 = g_srcA[i + 1], s2 = g_srcA[i + 2], s3 = g_srcA[i + 3];
                    a += (tin[s0 * 32 + lane] + tin[s1 * 32 + lane]) +
                         (tin[s2 * 32 + lane] + tin[s3 * 32 + lane]);
                }
                for (; i < eo; i++) a += tin[g_srcA[i] * 32 + lane];
                Asm[nl * 65 + lane] = a * nm;
            }
        }
    }
    __syncthreads();

    // ---- Phase 2: GEMM, thread = 4 nodes x 8 outs ----
    const int ty = tid >> 3, tx = tid & 7;
    float acc[32];
#pragma unroll
    for (int i = 0; i < 32; i++) acc[i] = 0.f;

#pragma unroll 8
    for (int k = 0; k < K; k++) {
        float a[4];
#pragma unroll
        for (int i = 0; i < 4; i++) a[i] = Asm[(ty * 4 + i) * 65 + k];
        const float4 w0 = *(const float4*)(Wsm + k * 64 + tx * 8);
        const float4 w1 = *(const float4*)(Wsm + k * 64 + tx * 8 + 4);
#pragma unroll
        for (int i = 0; i < 4; i++) {
            acc[i * 8 + 0] += a[i] * w0.x;
            acc[i * 8 + 1] += a[i] * w0.y;
            acc[i * 8 + 2] += a[i] * w0.z;
            acc[i * 8 + 3] += a[i] * w0.w;
            acc[i * 8 + 4] += a[i] * w1.x;
            acc[i * 8 + 5] += a[i] * w1.y;
            acc[i * 8 + 6] += a[i] * w1.z;
            acc[i * 8 + 7] += a[i] * w1.w;
        }
    }

    if (EPI == 0 || EPI == 2) {
#pragma unroll
        for (int i = 0; i < 4; i++) {
            int gn = base + ty * 4 + i;
            if (gn >= N) continue;
            float nm = g_norm[gn];
            float r[8];
#pragma unroll
            for (int j = 0; j < 8; j++) {
                float v = acc[i * 8 + j] + Bsm[tx * 8 + j];
                if (EPI == 0) v = fmaxf(v, 0.f) * nm;
                else          v = 1.f / (1.f + expf(-v));
                r[j] = v;
            }
            float* outp = (EPI == 0) ? tout : o0;
            *(float4*)(outp + (long long)gn * 64 + tx * 8)     = make_float4(r[0], r[1], r[2], r[3]);
            *(float4*)(outp + (long long)gn * 64 + tx * 8 + 4) = make_float4(r[4], r[5], r[6], r[7]);
        }
    } else {
        // EPI 1: stage pre-activation, then mu/lv/z
        __syncthreads();
#pragma unroll
        for (int i = 0; i < 4; i++)
#pragma unroll
            for (int j = 0; j < 8; j++)
                Asm[(ty * 4 + i) * 65 + tx * 8 + j] = acc[i * 8 + j] + Bsm[tx * 8 + j];
        __syncthreads();
        // 256 threads x 16 elems = 128 nodes x 32 channels
        int node = tid >> 1;
        int c0 = (tid & 1) * 16;
        int gn = base + node;
        if (gn < N) {
            float nm = g_norm[gn];
#pragma unroll
            for (int j = 0; j < 16; j++) {
                int c = c0 + j;
                float mu = Asm[node * 65 + c];
                float lv = Asm[node * 65 + c + 32];
                long long idx = (long long)gn * 32 + c;
                if (have) { o0[idx] = mu; o1[idx] = lv; }
                float z = eps[idx] * expf(0.5f * lv) + mu;
                tout[idx] = z * nm;
            }
        }
    }
}

// ---------------- launch --------------------------------------------------------
extern "C" void kernel_launch(void* const* d_in, const int* in_sizes, int n_in,
                              void* d_out, int out_size) {
    const int T = 256;
    auto G = [&](long long c) { return (int)((c + T - 1) / T); };
    float* outp = (float*)d_out;

    int N = in_sizes[0] / 64;
    int E = in_sizes[1];
    if (N > MAXN) N = MAXN;
    if (E > MAXE) E = MAXE;
    bool full_out = (out_size >= N * 128);
    (void)n_in;

    const float* x   = (const float*)d_in[0];
    const int* esrc  = (const int*)d_in[1];
    const int* edst  = (const int*)d_in[2];
    const float* eps = (const float*)d_in[3];
    const float* W1  = (const float*)d_in[4];  const float* b1  = (const float*)d_in[5];
    const float* W2  = (const float*)d_in[6];  const float* b2  = (const float*)d_in[7];
    const float* W31 = (const float*)d_in[8];  const float* b31 = (const float*)d_in[9];
    const float* W32 = (const float*)d_in[10]; const float* b32 = (const float*)d_in[11];
    const float* W4  = (const float*)d_in[12]; const float* b4  = (const float*)d_in[13];
    const float* W5  = (const float*)d_in[14]; const float* b5  = (const float*)d_in[15];
    const float* W6  = (const float*)d_in[16]; const float* b6  = (const float*)d_in[17];

    float* recon = outp;                          // N x 64
    float* d_mu  = outp + (long long)N * 64;      // N x 32
    float* d_lv  = d_mu + (long long)N * 32;      // N x 32

    const int SM64 = (128 * 65 + 64 * 64 + 64) * 4;   // 49920 B
    const int SM32 = (128 * 65 + 32 * 64 + 64) * 4;   // 41728 B
    cudaFuncSetAttribute(kfused<64, 0>, cudaFuncAttributeMaxDynamicSharedMemorySize, SM64);
    cudaFuncSetAttribute(kfused<64, 1>, cudaFuncAttributeMaxDynamicSharedMemorySize, SM64);
    cudaFuncSetAttribute(kfused<64, 2>, cudaFuncAttributeMaxDynamicSharedMemorySize, SM64);
    cudaFuncSetAttribute(kfused<32, 0>, cudaFuncAttributeMaxDynamicSharedMemorySize, SM32);

    if (out_size != N * 128)
        kfill_out<<<G(out_size), T>>>(outp, out_size);

    kz_deg<<<G(N), T>>>(N);
    kdeg<<<G(E), T>>>(edst, E);
    knorm<<<G(N), T>>>(N);
    kscan<<<1, 1024>>>(N);
    kcsr<<<G(E), T>>>(esrc, edst, E);

    kt0<<<G((long long)N * 64), T>>>(x, N * 64);   // writes g_t0 (pp=0)

    const int GB = (N + 127) / 128;
    int hv = full_out ? 1 : 0;

    // ping-pong: layer L reads buffer (L % 2), writes the other
    kfused<64, 0><<<GB, 256, SM64>>>(W1, nullptr, b1, nullptr, nullptr, nullptr, nullptr, N, 0, 0);
    kfused<64, 0><<<GB, 256, SM64>>>(W2, nullptr, b2, nullptr, nullptr, nullptr, nullptr, N, 0, 1);
    kfused<64, 1><<<GB, 256, SM64>>>(W31, W32, b31, b32, d_mu, d_lv, eps, N, hv, 0);
    kfused<32, 0><<<GB, 256, SM32>>>(W4, nullptr, b4, nullptr, nullptr, nullptr, nullptr, N, 0, 1);
    kfused<64, 0><<<GB, 256, SM64>>>(W5, nullptr, b5, nullptr, nullptr, nullptr, nullptr, N, 0, 0);
    kfused<64, 2><<<GB, 256, SM64>>>(W6, nullptr, b6, nullptr, recon, nullptr, nullptr, N, 0, 1);
}

// round 12
// speedup vs baseline: 1.6279x; 1.6279x over previous
#include <cuda_runtime.h>
#include <math.h>

#define MAXN 100000
#define MAXE 1600000

// ---------------- static device scratch (device-code use ONLY) -----------------
__device__ int   g_deg[MAXN];
__device__ int   g_off[MAXN + 1];
__device__ int   g_cur[MAXN];
__device__ int   g_part[1024];
__device__ int   g_srcA[MAXE];       // CSR: incoming-edge sources per dst node
__device__ float g_norm[MAXN];
__device__ float g_t[MAXN * 64];     // messages: h * norm
__device__ float g_agg[MAXN * 64];   // aggregation output (* norm applied)

// ---------------- graph preprocessing ------------------------------------------
__global__ void kz_deg(int n) {
    int i = blockIdx.x * blockDim.x + threadIdx.x;
    if (i < n) g_deg[i] = 0;
}
__global__ void kfill_out(float* __restrict__ p, int c) {
    int i = blockIdx.x * blockDim.x + threadIdx.x;
    if (i < c) p[i] = 0.0f;
}
__global__ void kdeg(const int* __restrict__ dst, int E) {
    int e = blockIdx.x * blockDim.x + threadIdx.x;
    if (e < E) atomicAdd(&g_deg[dst[e]], 1);
}
__global__ void knorm(int n) {
    int i = blockIdx.x * blockDim.x + threadIdx.x;
    if (i < n) g_norm[i] = rsqrtf(fmaxf((float)g_deg[i], 1.0f));
}

// ---- 3-pass exclusive scan of g_deg[0..N) -> g_off, g_cur ----
// pass1: per-block (1024-wide) local exclusive scan into g_off; block sums -> g_part
__global__ void kscan1(int N) {
    __shared__ int sh[1024];
    int tid = threadIdx.x;
    int i = blockIdx.x * 1024 + tid;
    int v = (i < N) ? g_deg[i] : 0;
    sh[tid] = v;
    __syncthreads();
    for (int off = 1; off < 1024; off <<= 1) {
        int t = (tid >= off) ? sh[tid - off] : 0;
        __syncthreads();
        sh[tid] += t;
        __syncthreads();
    }
    if (i < N) g_off[i] = sh[tid] - v;           // local exclusive
    if (tid == 1023) g_part[blockIdx.x] = sh[1023];
}
// pass2: single block scans <=1024 block partials (exclusive); total -> g_off[N]
__global__ void kscan2(int nb, int N) {
    __shared__ int sh[1024];
    int tid = threadIdx.x;
    int v = (tid < nb) ? g_part[tid] : 0;
    sh[tid] = v;
    __syncthreads();
    for (int off = 1; off < 1024; off <<= 1) {
        int t = (tid >= off) ? sh[tid - off] : 0;
        __syncthreads();
        sh[tid] += t;
        __syncthreads();
    }
    if (tid < nb) g_part[tid] = sh[tid] - v;     // exclusive block offsets
    if (tid == 1023) g_off[N] = sh[1023];        // total = E
}
// pass3: add block offsets; mirror into g_cur
__global__ void kscan3(int N) {
    int i = blockIdx.x * 1024 + threadIdx.x;
    if (i < N) {
        int o = g_off[i] + g_part[blockIdx.x];
        g_off[i] = o;
        g_cur[i] = o;
    }
}

__global__ void kcsr(const int* __restrict__ src, const int* __restrict__ dst, int E) {
    int e = blockIdx.x * blockDim.x + threadIdx.x;
    if (e < E) {
        int p = atomicAdd(&g_cur[dst[e]], 1);
        g_srcA[p] = src[e];
    }
}

__global__ void kt0(const float* __restrict__ x, int c) {
    int i = blockIdx.x * blockDim.x + threadIdx.x;
    if (i < c) g_t[i] = x[i] * g_norm[i >> 6];
}

// ---------------- aggregation (pull over CSR) ----------------------------------
// one warp per dst node; 64 feats: lane owns float2
__global__ __launch_bounds__(256) void kagg64(int N) {
    int n = blockIdx.x * 8 + (threadIdx.x >> 5);
    if (n >= N) return;
    int lane = threadIdx.x & 31;
    int b = g_off[n], e = g_off[n + 1];
    const float2* tp = (const float2*)g_t;
    float ax = 0.f, ay = 0.f;
    int i = b;
    for (; i + 4 <= e; i += 4) {
        int s0 = g_srcA[i], s1 = g_srcA[i + 1], s2 = g_srcA[i + 2], s3 = g_srcA[i + 3];
        float2 v0 = tp[s0 * 32 + lane];
        float2 v1 = tp[s1 * 32 + lane];
        float2 v2 = tp[s2 * 32 + lane];
        float2 v3 = tp[s3 * 32 + lane];
        ax += (v0.x + v1.x) + (v2.x + v3.x);
        ay += (v0.y + v1.y) + (v2.y + v3.y);
    }
    for (; i < e; i++) {
        float2 v = tp[g_srcA[i] * 32 + lane];
        ax += v.x; ay += v.y;
    }
    float nm = g_norm[n];
    ((float2*)g_agg)[n * 32 + lane] = make_float2(ax * nm, ay * nm);
}

// 32 feats: lane owns 1 float
__global__ __launch_bounds__(256) void kagg32(int N) {
    int n = blockIdx.x * 8 + (threadIdx.x >> 5);
    if (n >= N) return;
    int lane = threadIdx.x & 31;
    int b = g_off[n], e = g_off[n + 1];
    float a = 0.f;
    int i = b;
    for (; i + 4 <= e; i += 4) {
        int s0 = g_srcA[i], s1 = g_srcA[i + 1], s2 = g_srcA[i + 2], s3 = g_srcA[i + 3];
        a += (g_t[s0 * 32 + lane] + g_t[s1 * 32 + lane]) +
             (g_t[s2 * 32 + lane] + g_t[s3 * 32 + lane]);
    }
    for (; i < e; i++) a += g_t[g_srcA[i] * 32 + lane];
    g_agg[n * 32 + lane] = a * g_norm[n];
}

// ---------------- tiled GEMM: epi(g_agg[NxK] @ W.T + bias) ---------------------
// 128 threads; tile 128 nodes x 64 outs; thread = 8 nodes x 8 outs.
template <int K, int EPI>
__global__ __launch_bounds__(128) void kgemm(
    const float* __restrict__ Wa, const float* __restrict__ Wb,
    const float* __restrict__ bias0, const float* __restrict__ bias1,
    float* __restrict__ o0, float* __restrict__ o1, const float* __restrict__ eps,
    int N, int have)
{
    extern __shared__ float sm[];
    float* Asm = sm;                  // 128 * 65
    float* Wsm = sm + 128 * 65;       // K * 64   (Wsm[k*64+o] = W[o][k])
    float* Bsm = Wsm + K * 64;        // 64
    const int tid = threadIdx.x;
    const int base = blockIdx.x * 128;
    const float* __restrict__ A = g_agg;

    const int QUADS = 128 * (K / 4);
    for (int q = tid; q < QUADS; q += 128) {
        int node = q / (K / 4), kq = q % (K / 4);
        int gn = base + node;
        float4 v = make_float4(0.f, 0.f, 0.f, 0.f);
        if (gn < N) v = *(const float4*)(A + (long long)gn * K + kq * 4);
        float* p = Asm + node * 65 + kq * 4;
        p[0] = v.x; p[1] = v.y; p[2] = v.z; p[3] = v.w;
    }
    for (int q = tid; q < K * 64; q += 128) {
        int k = q >> 6, o = q & 63;
        float w;
        if (EPI == 1) w = (o < 32) ? Wa[o * 64 + k] : Wb[(o - 32) * 64 + k];
        else          w = Wa[o * K + k];
        Wsm[q] = w;
    }
    if (tid < 64) {
        if (EPI == 1) Bsm[tid] = (tid < 32) ? bias0[tid] : bias1[tid - 32];
        else          Bsm[tid] = bias0[tid];
    }
    __syncthreads();

    const int ty = tid >> 3, tx = tid & 7;
    float acc[64];
#pragma unroll
    for (int i = 0; i < 64; i++) acc[i] = 0.f;

#pragma unroll 8
    for (int k = 0; k < K; k++) {
        float a[8];
#pragma unroll
        for (int i = 0; i < 8; i++) a[i] = Asm[(ty * 8 + i) * 65 + k];
        const float4 w0 = *(const float4*)(Wsm + k * 64 + tx * 8);
        const float4 w1 = *(const float4*)(Wsm + k * 64 + tx * 8 + 4);
#pragma unroll
        for (int i = 0; i < 8; i++) {
            acc[i * 8 + 0] += a[i] * w0.x;
            acc[i * 8 + 1] += a[i] * w0.y;
            acc[i * 8 + 2] += a[i] * w0.z;
            acc[i * 8 + 3] += a[i] * w0.w;
            acc[i * 8 + 4] += a[i] * w1.x;
            acc[i * 8 + 5] += a[i] * w1.y;
            acc[i * 8 + 6] += a[i] * w1.z;
            acc[i * 8 + 7] += a[i] * w1.w;
        }
    }

    if (EPI == 0 || EPI == 2) {
#pragma unroll
        for (int i = 0; i < 8; i++) {
            int gn = base + ty * 8 + i;
            if (gn >= N) continue;
            float nm = g_norm[gn];
            float r[8];
#pragma unroll
            for (int j = 0; j < 8; j++) {
                float v = acc[i * 8 + j] + Bsm[tx * 8 + j];
                if (EPI == 0) v = fmaxf(v, 0.f) * nm;
                else          v = 1.f / (1.f + expf(-v));
                r[j] = v;
            }
            float* outp = (EPI == 0) ? g_t : o0;
            *(float4*)(outp + (long long)gn * 64 + tx * 8)     = make_float4(r[0], r[1], r[2], r[3]);
            *(float4*)(outp + (long long)gn * 64 + tx * 8 + 4) = make_float4(r[4], r[5], r[6], r[7]);
        }
    } else {
        __syncthreads();
#pragma unroll
        for (int i = 0; i < 8; i++)
#pragma unroll
            for (int j = 0; j < 8; j++)
                Asm[(ty * 8 + i) * 65 + tx * 8 + j] = acc[i * 8 + j] + Bsm[tx * 8 + j];
        __syncthreads();
#pragma unroll
        for (int i = 0; i < 8; i++) {
            int node = ty * 8 + i;
            int gn = base + node;
            if (gn >= N) continue;
            float nm = g_norm[gn];
#pragma unroll
            for (int j = 0; j < 4; j++) {
                int c = tx * 4 + j;
                float mu = Asm[node * 65 + c];
                float lv = Asm[node * 65 + c + 32];
                long long idx = (long long)gn * 32 + c;
                if (have) { o0[idx] = mu; o1[idx] = lv; }
                float z = eps[idx] * expf(0.5f * lv) + mu;
                g_t[idx] = z * nm;
            }
        }
    }
}

// ---------------- launch --------------------------------------------------------
extern "C" void kernel_launch(void* const* d_in, const int* in_sizes, int n_in,
                              void* d_out, int out_size) {
    const int T = 256;
    auto G = [&](long long c) { return (int)((c + T - 1) / T); };
    float* outp = (float*)d_out;

    int N = in_sizes[0] / 64;
    int E = in_sizes[1];
    if (N > MAXN) N = MAXN;
    if (E > MAXE) E = MAXE;
    bool full_out = (out_size >= N * 128);
    (void)n_in;

    const float* x   = (const float*)d_in[0];
    const int* esrc  = (const int*)d_in[1];
    const int* edst  = (const int*)d_in[2];
    const float* eps = (const float*)d_in[3];
    const float* W1  = (const float*)d_in[4];  const float* b1  = (const float*)d_in[5];
    const float* W2  = (const float*)d_in[6];  const float* b2  = (const float*)d_in[7];
    const float* W31 = (const float*)d_in[8];  const float* b31 = (const float*)d_in[9];
    const float* W32 = (const float*)d_in[10]; const float* b32 = (const float*)d_in[11];
    const float* W4  = (const float*)d_in[12]; const float* b4  = (const float*)d_in[13];
    const float* W5  = (const float*)d_in[14]; const float* b5  = (const float*)d_in[15];
    const float* W6  = (const float*)d_in[16]; const float* b6  = (const float*)d_in[17];

    float* recon = outp;                          // N x 64
    float* d_mu  = outp + (long long)N * 64;      // N x 32
    float* d_lv  = d_mu + (long long)N * 32;      // N x 32

    const int SM64 = (128 * 65 + 64 * 64 + 64) * 4;
    const int SM32 = (128 * 65 + 32 * 64 + 64) * 4;
    cudaFuncSetAttribute(kgemm<64, 0>, cudaFuncAttributeMaxDynamicSharedMemorySize, SM64);
    cudaFuncSetAttribute(kgemm<64, 1>, cudaFuncAttributeMaxDynamicSharedMemorySize, SM64);
    cudaFuncSetAttribute(kgemm<64, 2>, cudaFuncAttributeMaxDynamicSharedMemorySize, SM64);
    cudaFuncSetAttribute(kgemm<32, 0>, cudaFuncAttributeMaxDynamicSharedMemorySize, SM32);

    if (out_size != N * 128)
        kfill_out<<<G(out_size), T>>>(outp, out_size);

    kz_deg<<<G(N), T>>>(N);
    kdeg<<<G(E), T>>>(edst, E);
    knorm<<<G(N), T>>>(N);

    int nb = (N + 1023) / 1024;      // <= 1024 for N <= 1M
    kscan1<<<nb, 1024>>>(N);
    kscan2<<<1, 1024>>>(nb, N);
    kscan3<<<nb, 1024>>>(N);

    kcsr<<<G(E), T>>>(esrc, edst, E);

    kt0<<<G((long long)N * 64), T>>>(x, N * 64);

    const int AB = (N + 7) / 8;
    const int GB = (N + 127) / 128;
    int hv = full_out ? 1 : 0;

    kagg64<<<AB, 256>>>(N);
    kgemm<64, 0><<<GB, 128, SM64>>>(W1, nullptr, b1, nullptr, nullptr, nullptr, nullptr, N, 0);
    kagg64<<<AB, 256>>>(N);
    kgemm<64, 0><<<GB, 128, SM64>>>(W2, nullptr, b2, nullptr, nullptr, nullptr, nullptr, N, 0);
    kagg64<<<AB, 256>>>(N);
    kgemm<64, 1><<<GB, 128, SM64>>>(W31, W32, b31, b32, d_mu, d_lv, eps, N, hv);
    kagg32<<<AB, 256>>>(N);
    kgemm<32, 0><<<GB, 128, SM32>>>(W4, nullptr, b4, nullptr, nullptr, nullptr, nullptr, N, 0);
    kagg64<<<AB, 256>>>(N);
    kgemm<64, 0><<<GB, 128, SM64>>>(W5, nullptr, b5, nullptr, nullptr, nullptr, nullptr, N, 0);
    kagg64<<<AB, 256>>>(N);
    kgemm<64, 2><<<GB, 128, SM64>>>(W6, nullptr, b6, nullptr, recon, nullptr, nullptr, N, 0);
}

// round 13
// speedup vs baseline: 1.7094x; 1.0501x over previous
#include <cuda_runtime.h>
#include <cuda_fp16.h>
#include <math.h>

#define MAXN 100000
#define MAXE 1600000

// ---------------- static device scratch (device-code use ONLY) -----------------
__device__ int    g_deg[MAXN];
__device__ int    g_off[MAXN + 1];
__device__ int    g_cur[MAXN];
__device__ int    g_part[1024];
__device__ int    g_srcA[MAXE];       // CSR: incoming-edge sources per dst node
__device__ float  g_norm[MAXN];
__device__ __half g_t[MAXN * 64];     // messages: h * norm (fp16 storage, fp32 math)
__device__ float  g_agg[MAXN * 64];   // aggregation output (* norm applied), fp32

// ---------------- graph preprocessing ------------------------------------------
__global__ void kz_deg(int n) {
    int i = blockIdx.x * blockDim.x + threadIdx.x;
    if (i < n) g_deg[i] = 0;
}
__global__ void kfill_out(float* __restrict__ p, int c) {
    int i = blockIdx.x * blockDim.x + threadIdx.x;
    if (i < c) p[i] = 0.0f;
}
__global__ void kdeg(const int* __restrict__ dst, int E) {
    int e = blockIdx.x * blockDim.x + threadIdx.x;
    if (e < E) atomicAdd(&g_deg[dst[e]], 1);
}
__global__ void knorm(int n) {
    int i = blockIdx.x * blockDim.x + threadIdx.x;
    if (i < n) g_norm[i] = rsqrtf(fmaxf((float)g_deg[i], 1.0f));
}

// ---- 3-pass exclusive scan of g_deg[0..N) -> g_off, g_cur ----
__global__ void kscan1(int N) {
    __shared__ int sh[1024];
    int tid = threadIdx.x;
    int i = blockIdx.x * 1024 + tid;
    int v = (i < N) ? g_deg[i] : 0;
    sh[tid] = v;
    __syncthreads();
    for (int off = 1; off < 1024; off <<= 1) {
        int t = (tid >= off) ? sh[tid - off] : 0;
        __syncthreads();
        sh[tid] += t;
        __syncthreads();
    }
    if (i < N) g_off[i] = sh[tid] - v;
    if (tid == 1023) g_part[blockIdx.x] = sh[1023];
}
__global__ void kscan2(int nb, int N) {
    __shared__ int sh[1024];
    int tid = threadIdx.x;
    int v = (tid < nb) ? g_part[tid] : 0;
    sh[tid] = v;
    __syncthreads();
    for (int off = 1; off < 1024; off <<= 1) {
        int t = (tid >= off) ? sh[tid - off] : 0;
        __syncthreads();
        sh[tid] += t;
        __syncthreads();
    }
    if (tid < nb) g_part[tid] = sh[tid] - v;
    if (tid == 1023) g_off[N] = sh[1023];
}
__global__ void kscan3(int N) {
    int i = blockIdx.x * 1024 + threadIdx.x;
    if (i < N) {
        int o = g_off[i] + g_part[blockIdx.x];
        g_off[i] = o;
        g_cur[i] = o;
    }
}

__global__ void kcsr(const int* __restrict__ src, const int* __restrict__ dst, int E) {
    int e = blockIdx.x * blockDim.x + threadIdx.x;
    if (e < E) {
        int p = atomicAdd(&g_cur[dst[e]], 1);
        g_srcA[p] = src[e];
    }
}

__global__ void kt0(const float* __restrict__ x, int c) {
    int i = blockIdx.x * blockDim.x + threadIdx.x;
    if (i < c) g_t[i] = __float2half_rn(x[i] * g_norm[i >> 6]);
}

// ---------------- aggregation (pull over CSR, fp16 msgs, fp32 accum) ------------
// one warp per dst node; 64 feats: lane owns half2 (2 dims)
__global__ __launch_bounds__(256) void kagg64(int N) {
    int n = blockIdx.x * 8 + (threadIdx.x >> 5);
    if (n >= N) return;
    int lane = threadIdx.x & 31;
    int b = g_off[n], e = g_off[n + 1];
    const __half2* tp = (const __half2*)g_t;
    float ax = 0.f, ay = 0.f;
    int i = b;
    for (; i + 8 <= e; i += 8) {
        float2 f[8];
#pragma unroll
        for (int u = 0; u < 8; u++) {
            int s = g_srcA[i + u];
            f[u] = __half22float2(tp[s * 32 + lane]);
        }
#pragma unroll
        for (int u = 0; u < 8; u++) { ax += f[u].x; ay += f[u].y; }
    }
    for (; i < e; i++) {
        float2 v = __half22float2(tp[g_srcA[i] * 32 + lane]);
        ax += v.x; ay += v.y;
    }
    float nm = g_norm[n];
    ((float2*)g_agg)[n * 32 + lane] = make_float2(ax * nm, ay * nm);
}

// 32 feats: lane owns 1 half
__global__ __launch_bounds__(256) void kagg32(int N) {
    int n = blockIdx.x * 8 + (threadIdx.x >> 5);
    if (n >= N) return;
    int lane = threadIdx.x & 31;
    int b = g_off[n], e = g_off[n + 1];
    float a = 0.f;
    int i = b;
    for (; i + 8 <= e; i += 8) {
        float f[8];
#pragma unroll
        for (int u = 0; u < 8; u++) {
            int s = g_srcA[i + u];
            f[u] = __half2float(g_t[s * 32 + lane]);
        }
#pragma unroll
        for (int u = 0; u < 8; u++) a += f[u];
    }
    for (; i < e; i++) a += __half2float(g_t[g_srcA[i] * 32 + lane]);
    g_agg[n * 32 + lane] = a * g_norm[n];
}

// ---------------- tiled GEMM: epi(g_agg[NxK] @ W.T + bias) ---------------------
// 128 threads; tile 128 nodes x 64 outs; thread = 8 nodes x 8 outs.
// EPI 0: relu * norm -> g_t fp16 (stride 64)
// EPI 1: mu -> o0, lv -> o1 (if have), z*norm -> g_t fp16 (stride 32)
// EPI 2: sigmoid -> o0 fp32 (recon)
template <int K, int EPI>
__global__ __launch_bounds__(128) void kgemm(
    const float* __restrict__ Wa, const float* __restrict__ Wb,
    const float* __restrict__ bias0, const float* __restrict__ bias1,
    float* __restrict__ o0, float* __restrict__ o1, const float* __restrict__ eps,
    int N, int have)
{
    extern __shared__ float sm[];
    float* Asm = sm;                  // 128 * 65
    float* Wsm = sm + 128 * 65;       // K * 64   (Wsm[k*64+o] = W[o][k])
    float* Bsm = Wsm + K * 64;        // 64
    const int tid = threadIdx.x;
    const int base = blockIdx.x * 128;
    const float* __restrict__ A = g_agg;

    const int QUADS = 128 * (K / 4);
    for (int q = tid; q < QUADS; q += 128) {
        int node = q / (K / 4), kq = q % (K / 4);
        int gn = base + node;
        float4 v = make_float4(0.f, 0.f, 0.f, 0.f);
        if (gn < N) v = *(const float4*)(A + (long long)gn * K + kq * 4);
        float* p = Asm + node * 65 + kq * 4;
        p[0] = v.x; p[1] = v.y; p[2] = v.z; p[3] = v.w;
    }
    for (int q = tid; q < K * 64; q += 128) {
        int k = q >> 6, o = q & 63;
        float w;
        if (EPI == 1) w = (o < 32) ? Wa[o * 64 + k] : Wb[(o - 32) * 64 + k];
        else          w = Wa[o * K + k];
        Wsm[q] = w;
    }
    if (tid < 64) {
        if (EPI == 1) Bsm[tid] = (tid < 32) ? bias0[tid] : bias1[tid - 32];
        else          Bsm[tid] = bias0[tid];
    }
    __syncthreads();

    const int ty = tid >> 3, tx = tid & 7;
    float acc[64];
#pragma unroll
    for (int i = 0; i < 64; i++) acc[i] = 0.f;

#pragma unroll 8
    for (int k = 0; k < K; k++) {
        float a[8];
#pragma unroll
        for (int i = 0; i < 8; i++) a[i] = Asm[(ty * 8 + i) * 65 + k];
        const float4 w0 = *(const float4*)(Wsm + k * 64 + tx * 8);
        const float4 w1 = *(const float4*)(Wsm + k * 64 + tx * 8 + 4);
#pragma unroll
        for (int i = 0; i < 8; i++) {
            acc[i * 8 + 0] += a[i] * w0.x;
            acc[i * 8 + 1] += a[i] * w0.y;
            acc[i * 8 + 2] += a[i] * w0.z;
            acc[i * 8 + 3] += a[i] * w0.w;
            acc[i * 8 + 4] += a[i] * w1.x;
            acc[i * 8 + 5] += a[i] * w1.y;
            acc[i * 8 + 6] += a[i] * w1.z;
            acc[i * 8 + 7] += a[i] * w1.w;
        }
    }

    if (EPI == 0) {
#pragma unroll
        for (int i = 0; i < 8; i++) {
            int gn = base + ty * 8 + i;
            if (gn >= N) continue;
            float nm = g_norm[gn];
            __half2 h[4];
#pragma unroll
            for (int j = 0; j < 4; j++) {
                float v0 = fmaxf(acc[i * 8 + 2 * j]     + Bsm[tx * 8 + 2 * j], 0.f) * nm;
                float v1 = fmaxf(acc[i * 8 + 2 * j + 1] + Bsm[tx * 8 + 2 * j + 1], 0.f) * nm;
                h[j] = __floats2half2_rn(v0, v1);
            }
            __half2* row = (__half2*)(g_t + (long long)gn * 64);
            row[tx * 4 + 0] = h[0];
            row[tx * 4 + 1] = h[1];
            row[tx * 4 + 2] = h[2];
            row[tx * 4 + 3] = h[3];
        }
    } else if (EPI == 2) {
#pragma unroll
        for (int i = 0; i < 8; i++) {
            int gn = base + ty * 8 + i;
            if (gn >= N) continue;
            float r[8];
#pragma unroll
            for (int j = 0; j < 8; j++) {
                float v = acc[i * 8 + j] + Bsm[tx * 8 + j];
                r[j] = 1.f / (1.f + expf(-v));
            }
            *(float4*)(o0 + (long long)gn * 64 + tx * 8)     = make_float4(r[0], r[1], r[2], r[3]);
            *(float4*)(o0 + (long long)gn * 64 + tx * 8 + 4) = make_float4(r[4], r[5], r[6], r[7]);
        }
    } else {
        __syncthreads();
#pragma unroll
        for (int i = 0; i < 8; i++)
#pragma unroll
            for (int j = 0; j < 8; j++)
                Asm[(ty * 8 + i) * 65 + tx * 8 + j] = acc[i * 8 + j] + Bsm[tx * 8 + j];
        __syncthreads();
#pragma unroll
        for (int i = 0; i < 8; i++) {
            int node = ty * 8 + i;
            int gn = base + node;
            if (gn >= N) continue;
            float nm = g_norm[gn];
#pragma unroll
            for (int j = 0; j < 4; j++) {
                int c = tx * 4 + j;
                float mu = Asm[node * 65 + c];
                float lv = Asm[node * 65 + c + 32];
                long long idx = (long long)gn * 32 + c;
                if (have) { o0[idx] = mu; o1[idx] = lv; }
                float z = eps[idx] * expf(0.5f * lv) + mu;
                g_t[idx] = __float2half_rn(z * nm);
            }
        }
    }
}

// ---------------- launch --------------------------------------------------------
extern "C" void kernel_launch(void* const* d_in, const int* in_sizes, int n_in,
                              void* d_out, int out_size) {
    const int T = 256;
    auto G = [&](long long c) { return (int)((c + T - 1) / T); };
    float* outp = (float*)d_out;

    int N = in_sizes[0] / 64;
    int E = in_sizes[1];
    if (N > MAXN) N = MAXN;
    if (E > MAXE) E = MAXE;
    bool full_out = (out_size >= N * 128);
    (void)n_in;

    const float* x   = (const float*)d_in[0];
    const int* esrc  = (const int*)d_in[1];
    const int* edst  = (const int*)d_in[2];
    const float* eps = (const float*)d_in[3];
    const float* W1  = (const float*)d_in[4];  const float* b1  = (const float*)d_in[5];
    const float* W2  = (const float*)d_in[6];  const float* b2  = (const float*)d_in[7];
    const float* W31 = (const float*)d_in[8];  const float* b31 = (const float*)d_in[9];
    const float* W32 = (const float*)d_in[10]; const float* b32 = (const float*)d_in[11];
    const float* W4  = (const float*)d_in[12]; const float* b4  = (const float*)d_in[13];
    const float* W5  = (const float*)d_in[14]; const float* b5  = (const float*)d_in[15];
    const float* W6  = (const float*)d_in[16]; const float* b6  = (const float*)d_in[17];

    float* recon = outp;                          // N x 64
    float* d_mu  = outp + (long long)N * 64;      // N x 32
    float* d_lv  = d_mu + (long long)N * 32;      // N x 32

    const int SM64 = (128 * 65 + 64 * 64 + 64) * 4;
    const int SM32 = (128 * 65 + 32 * 64 + 64) * 4;
    cudaFuncSetAttribute(kgemm<64, 0>, cudaFuncAttributeMaxDynamicSharedMemorySize, SM64);
    cudaFuncSetAttribute(kgemm<64, 1>, cudaFuncAttributeMaxDynamicSharedMemorySize, SM64);
    cudaFuncSetAttribute(kgemm<64, 2>, cudaFuncAttributeMaxDynamicSharedMemorySize, SM64);
    cudaFuncSetAttribute(kgemm<32, 0>, cudaFuncAttributeMaxDynamicSharedMemorySize, SM32);

    if (out_size != N * 128)
        kfill_out<<<G(out_size), T>>>(outp, out_size);

    kz_deg<<<G(N), T>>>(N);
    kdeg<<<G(E), T>>>(edst, E);
    knorm<<<G(N), T>>>(N);

    int nb = (N + 1023) / 1024;
    kscan1<<<nb, 1024>>>(N);
    kscan2<<<1, 1024>>>(nb, N);
    kscan3<<<nb, 1024>>>(N);

    kcsr<<<G(E), T>>>(esrc, edst, E);

    kt0<<<G((long long)N * 64), T>>>(x, N * 64);

    const int AB = (N + 7) / 8;
    const int GB = (N + 127) / 128;
    int hv = full_out ? 1 : 0;

    kagg64<<<AB, 256>>>(N);
    kgemm<64, 0><<<GB, 128, SM64>>>(W1, nullptr, b1, nullptr, nullptr, nullptr, nullptr, N, 0);
    kagg64<<<AB, 256>>>(N);
    kgemm<64, 0><<<GB, 128, SM64>>>(W2, nullptr, b2, nullptr, nullptr, nullptr, nullptr, N, 0);
    kagg64<<<AB, 256>>>(N);
    kgemm<64, 1><<<GB, 128, SM64>>>(W31, W32, b31, b32, d_mu, d_lv, eps, N, hv);
    kagg32<<<AB, 256>>>(N);
    kgemm<32, 0><<<GB, 128, SM32>>>(W4, nullptr, b4, nullptr, nullptr, nullptr, nullptr, N, 0);
    kagg64<<<AB, 256>>>(N);
    kgemm<64, 0><<<GB, 128, SM64>>>(W5, nullptr, b5, nullptr, nullptr, nullptr, nullptr, N, 0);
    kagg64<<<AB, 256>>>(N);
    kgemm<64, 2><<<GB, 128, SM64>>>(W6, nullptr, b6, nullptr, recon, nullptr, nullptr, N, 0);
}